// round 5
// baseline (speedup 1.0000x reference)
#include <cuda_runtime.h>
#include <cstdint>

#define E_DIM 512
#define BM 128
#define BN 128
#define BK 16
#define TM 8
#define TN 8
#define NTHREADS 256

// Scratch (device globals: no allocation allowed in kernel_launch)
__device__ float g_xsq[16384];
__device__ float g_wsq[8192];
__device__ int   g_idx[16384];

// ---------------------------------------------------------------------------
// Kernel 1: row sums of squares for x (N rows) and weight (Q rows).
// One block (128 threads) per row; float4 loads; pairwise/tree reduction.
// ---------------------------------------------------------------------------
__global__ void sumsq_kernel(const float* __restrict__ x,
                             const float* __restrict__ w, int N) {
    int row = blockIdx.x;
    const float* src;
    float* dst;
    if (row < N) { src = x + (size_t)row * E_DIM;       dst = &g_xsq[row]; }
    else         { src = w + (size_t)(row - N) * E_DIM; dst = &g_wsq[row - N]; }
    int t = threadIdx.x;  // 128 threads, 4 floats each = 512
    float4 v = reinterpret_cast<const float4*>(src)[t];
    float s = (v.x * v.x + v.y * v.y) + (v.z * v.z + v.w * v.w);
    #pragma unroll
    for (int o = 16; o > 0; o >>= 1) s += __shfl_xor_sync(0xffffffffu, s, o);
    __shared__ float ws[4];
    if ((t & 31) == 0) ws[t >> 5] = s;
    __syncthreads();
    if (t == 0) *dst = (ws[0] + ws[1]) + (ws[2] + ws[3]);
}

// ---------------------------------------------------------------------------
// Kernel 2: fused distance GEMM + row argmin.
// C[n,q] = dot(x[n,:], w[q,:]);  val = (x_sq[n] - 2*C) + w_sq[q]  (matches the
// reference's fp32 rounding order exactly: fmaf(-2,dot,xs) == xs - (2*dot)
// since 2*dot is exact).  Running (min, idx) per row, tie -> lowest idx.
//
// Tiling: BM=128 x BN=128 x BK=16, 256 threads, 8x8 accum / thread,
// double-buffered shared memory, grid = N/128 = 128 CTAs (one wave).
// Each CTA sweeps all Q column-tiles for its 128 rows.
// ---------------------------------------------------------------------------
__global__ __launch_bounds__(NTHREADS)
void vq_argmin_kernel(const float* __restrict__ X,
                      const float* __restrict__ W, int N, int Q) {
    __shared__ float As[2][BK][BM];
    __shared__ float Bs[2][BK][BN];

    const int tid = threadIdx.x;
    const int tx = tid & 15;        // 0..15  (column group)
    const int ty = tid >> 4;        // 0..15  (row group)
    const int m0 = blockIdx.x * BM;

    // loader mapping: each thread loads rows (lr, lr+64), 4 consecutive k's
    const int lr = tid >> 2;        // 0..63
    const int lk = (tid & 3) << 2;  // 0,4,8,12

    const int nq = Q / BN;          // 64
    const int nk = E_DIM / BK;      // 32

    float acc[TM][TN];
    #pragma unroll
    for (int i = 0; i < TM; ++i)
        #pragma unroll
        for (int j = 0; j < TN; ++j) acc[i][j] = 0.f;

    float xs[TM];
    #pragma unroll
    for (int i = 0; i < TM; ++i) xs[i] = g_xsq[m0 + ty * TM + i];

    const float INF = __int_as_float(0x7f800000);
    float bestv[TM];
    int   besti[TM];
    #pragma unroll
    for (int i = 0; i < TM; ++i) { bestv[i] = INF; besti[i] = 0; }

    // --- prologue: load tile (qt=0, kt=0) ---
    const float* xp0 = X + (size_t)(m0 + lr) * E_DIM + lk;
    float4 pa0 = *(const float4*)(xp0);
    float4 pa1 = *(const float4*)(xp0 + 64 * E_DIM);
    const float* wp0 = W + (size_t)lr * E_DIM + lk;
    float4 pb0 = *(const float4*)(wp0);
    float4 pb1 = *(const float4*)(wp0 + 64 * E_DIM);

    int buf = 0;
    // store prologue tile into buffer 0
    {
        As[0][lk + 0][lr] = pa0.x; As[0][lk + 1][lr] = pa0.y;
        As[0][lk + 2][lr] = pa0.z; As[0][lk + 3][lr] = pa0.w;
        As[0][lk + 0][lr + 64] = pa1.x; As[0][lk + 1][lr + 64] = pa1.y;
        As[0][lk + 2][lr + 64] = pa1.z; As[0][lk + 3][lr + 64] = pa1.w;
        Bs[0][lk + 0][lr] = pb0.x; Bs[0][lk + 1][lr] = pb0.y;
        Bs[0][lk + 2][lr] = pb0.z; Bs[0][lk + 3][lr] = pb0.w;
        Bs[0][lk + 0][lr + 64] = pb1.x; Bs[0][lk + 1][lr + 64] = pb1.y;
        Bs[0][lk + 2][lr + 64] = pb1.z; Bs[0][lk + 3][lr + 64] = pb1.w;
    }
    __syncthreads();

    for (int qt = 0; qt < nq; ++qt) {
        for (int kt = 0; kt < nk; ++kt) {
            // prefetch next tile (flat (qt,kt) sequence) into registers
            int nqt = qt, nkt = kt + 1;
            if (nkt == nk) { nkt = 0; ++nqt; }
            const bool has_next = (nqt < nq);
            if (has_next) {
                const float* xp = X + (size_t)(m0 + lr) * E_DIM + nkt * BK + lk;
                pa0 = *(const float4*)(xp);
                pa1 = *(const float4*)(xp + 64 * E_DIM);
                const float* wp = W + (size_t)(nqt * BN + lr) * E_DIM + nkt * BK + lk;
                pb0 = *(const float4*)(wp);
                pb1 = *(const float4*)(wp + 64 * E_DIM);
            }

            // compute on current buffer
            #pragma unroll
            for (int k = 0; k < BK; ++k) {
                const float* ap = &As[buf][k][ty * TM];
                const float* bp = &Bs[buf][k][tx * TN];
                float4 a0 = *(const float4*)(ap);
                float4 a1 = *(const float4*)(ap + 4);
                float4 b0 = *(const float4*)(bp);
                float4 b1 = *(const float4*)(bp + 4);
                float av[TM] = {a0.x, a0.y, a0.z, a0.w, a1.x, a1.y, a1.z, a1.w};
                float bv[TN] = {b0.x, b0.y, b0.z, b0.w, b1.x, b1.y, b1.z, b1.w};
                #pragma unroll
                for (int i = 0; i < TM; ++i)
                    #pragma unroll
                    for (int j = 0; j < TN; ++j)
                        acc[i][j] = fmaf(av[i], bv[j], acc[i][j]);
            }

            if (has_next) {
                const int ob = buf ^ 1;
                As[ob][lk + 0][lr] = pa0.x; As[ob][lk + 1][lr] = pa0.y;
                As[ob][lk + 2][lr] = pa0.z; As[ob][lk + 3][lr] = pa0.w;
                As[ob][lk + 0][lr + 64] = pa1.x; As[ob][lk + 1][lr + 64] = pa1.y;
                As[ob][lk + 2][lr + 64] = pa1.z; As[ob][lk + 3][lr + 64] = pa1.w;
                Bs[ob][lk + 0][lr] = pb0.x; Bs[ob][lk + 1][lr] = pb0.y;
                Bs[ob][lk + 2][lr] = pb0.z; Bs[ob][lk + 3][lr] = pb0.w;
                Bs[ob][lk + 0][lr + 64] = pb1.x; Bs[ob][lk + 1][lr + 64] = pb1.y;
                Bs[ob][lk + 2][lr + 64] = pb1.z; Bs[ob][lk + 3][lr + 64] = pb1.w;
            }
            __syncthreads();
            buf ^= 1;
        }

        // --- epilogue for this q-tile: fold into running argmin ---
        const int q0 = qt * BN + tx * TN;
        float wsq[TN];
        #pragma unroll
        for (int j = 0; j < TN; ++j) wsq[j] = g_wsq[q0 + j];
        #pragma unroll
        for (int i = 0; i < TM; ++i) {
            #pragma unroll
            for (int j = 0; j < TN; ++j) {
                // (x_sq - 2*dot) + w_sq  — same rounding as the reference
                float v = fmaf(-2.0f, acc[i][j], xs[i]);
                v = v + wsq[j];
                const int q = q0 + j;
                if (v < bestv[i] || (v == bestv[i] && q < besti[i])) {
                    bestv[i] = v; besti[i] = q;
                }
                acc[i][j] = 0.f;
            }
        }
    }

    // cross-thread reduction over the 16 tx lanes sharing each row group.
    // Threads with the same ty are 16 consecutive lanes inside one warp,
    // so xor-shuffles with offsets 8,4,2,1 stay within the group.
    #pragma unroll
    for (int i = 0; i < TM; ++i) {
        float v = bestv[i];
        int   qi = besti[i];
        #pragma unroll
        for (int o = 8; o > 0; o >>= 1) {
            float v2 = __shfl_xor_sync(0xffffffffu, v, o);
            int   q2 = __shfl_xor_sync(0xffffffffu, qi, o);
            if (v2 < v || (v2 == v && q2 < qi)) { v = v2; qi = q2; }
        }
        if (tx == 0) g_idx[m0 + ty * TM + i] = qi;
    }
}

// ---------------------------------------------------------------------------
// Kernel 3: gather codebook rows + emit idx (as float, matching a float32
// concatenated output buffer). Fills every element of d_out (it is poisoned).
// ---------------------------------------------------------------------------
__global__ void gather_kernel(const float* __restrict__ W,
                              float* __restrict__ out,
                              int N, long long total) {
    long long p = (long long)blockIdx.x * blockDim.x + threadIdx.x;
    if (p >= total) return;
    const long long ne = (long long)N * E_DIM;
    if (p < ne) {
        int n = (int)(p >> 9);          // /512
        int e = (int)(p & 511);
        out[p] = W[(size_t)g_idx[n] * E_DIM + e];
    } else if (p < ne + N) {
        out[p] = (float)g_idx[p - ne];
    } else {
        out[p] = 0.f;
    }
}

// ---------------------------------------------------------------------------
extern "C" void kernel_launch(void* const* d_in, const int* in_sizes, int n_in,
                              void* d_out, int out_size) {
    const float* x = (const float*)d_in[0];   // (8,2048,512) fp32
    const float* w = (const float*)d_in[1];   // (8192,512)  fp32
    const int N = in_sizes[0] / E_DIM;        // 16384
    const int Q = in_sizes[1] / E_DIM;        // 8192

    sumsq_kernel<<<N + Q, 128>>>(x, w, N);
    vq_argmin_kernel<<<N / BM, NTHREADS>>>(x, w, N, Q);

    const long long total = (long long)out_size;
    const int thr = 256;
    const int blocks = (int)((total + thr - 1) / thr);
    gather_kernel<<<blocks, thr>>>(w, (float*)d_out, N, total);
}

// round 13
// speedup vs baseline: 4.3117x; 4.3117x over previous
#include <cuda_runtime.h>
#include <cuda_fp16.h>
#include <cuda_bf16.h>
#include <cstdint>

#define E_DIM 512
#define N_ROWS 16384
#define Q_ROWS 8192

// GEMM tiling: BM=128, BN=128, BK=32, 8 warps (2x4), warp tile 64x32
#define BM 128
#define BN 128
#define BK 32
#define GEMM_THREADS 256
// padded smem row stride: 32 bf16 = 64B data + 16B pad = 80B.
// MUST be a multiple of 16 (ldmatrix alignment). 80B -> row r starts at bank
// 20r mod 32 -> an 8-row LDSM phase covers all 32 banks once: conflict-free.
#define ROWB 80

#define MARGIN 0.0078125f

// ===== device scratch (static globals; no runtime allocation) =====
__device__ float g_xsq[N_ROWS];
__device__ float g_wsq[Q_ROWS];
__device__ int   g_idx[N_ROWS];
__device__ __align__(16) __nv_bfloat16 g_xb[N_ROWS * E_DIM];   // 16 MB
__device__ __align__(16) __nv_bfloat16 g_wb[Q_ROWS * E_DIM];   //  8 MB
__device__ __align__(16) __half2 g_s[(size_t)N_ROWS * (Q_ROWS / 2)]; // 256 MB

// ---------------------------------------------------------------------------
// PTX helpers (all sm_80-era features; compile fine at .target sm_103)
// ---------------------------------------------------------------------------
__device__ __forceinline__ uint32_t smem_u32(const void* p) {
    uint32_t a;
    asm("{ .reg .u64 t; cvta.to.shared.u64 t, %1; cvt.u32.u64 %0, t; }"
        : "=r"(a) : "l"(p));
    return a;
}
__device__ __forceinline__ void cp_async16(uint32_t dst, const void* src) {
    asm volatile("cp.async.ca.shared.global [%0], [%1], 16;"
                 :: "r"(dst), "l"(src) : "memory");
}
__device__ __forceinline__ void cp_commit() {
    asm volatile("cp.async.commit_group;" ::: "memory");
}
template <int N>
__device__ __forceinline__ void cp_wait() {
    asm volatile("cp.async.wait_group %0;" :: "n"(N) : "memory");
}
__device__ __forceinline__ void ldm_x4(uint32_t& r0, uint32_t& r1,
                                       uint32_t& r2, uint32_t& r3, uint32_t a) {
    asm volatile("ldmatrix.sync.aligned.m8n8.x4.shared.b16 {%0,%1,%2,%3}, [%4];"
                 : "=r"(r0), "=r"(r1), "=r"(r2), "=r"(r3) : "r"(a));
}
__device__ __forceinline__ void mma_bf16(float* d, const uint32_t* a,
                                         const uint32_t* b) {
    asm volatile(
        "mma.sync.aligned.m16n8k16.row.col.f32.bf16.bf16.f32 "
        "{%0,%1,%2,%3}, {%4,%5,%6,%7}, {%8,%9}, {%0,%1,%2,%3};"
        : "+f"(d[0]), "+f"(d[1]), "+f"(d[2]), "+f"(d[3])
        : "r"(a[0]), "r"(a[1]), "r"(a[2]), "r"(a[3]), "r"(b[0]), "r"(b[1]));
}

// ---------------------------------------------------------------------------
// Kernel 1: row sums of squares (unchanged — matched rel_err 0.0).
// ---------------------------------------------------------------------------
__global__ void sumsq_kernel(const float* __restrict__ x,
                             const float* __restrict__ w, int N) {
    int row = blockIdx.x;
    const float* src;
    float* dst;
    if (row < N) { src = x + (size_t)row * E_DIM;       dst = &g_xsq[row]; }
    else         { src = w + (size_t)(row - N) * E_DIM; dst = &g_wsq[row - N]; }
    int t = threadIdx.x;
    float4 v = reinterpret_cast<const float4*>(src)[t];
    float s = (v.x * v.x + v.y * v.y) + (v.z * v.z + v.w * v.w);
    #pragma unroll
    for (int o = 16; o > 0; o >>= 1) s += __shfl_xor_sync(0xffffffffu, s, o);
    __shared__ float ws[4];
    if ((t & 31) == 0) ws[t >> 5] = s;
    __syncthreads();
    if (t == 0) *dst = (ws[0] + ws[1]) + (ws[2] + ws[3]);
}

// ---------------------------------------------------------------------------
// Kernel 2: fp32 -> bf16 (rn). Each thread converts 8 consecutive floats.
// ---------------------------------------------------------------------------
#define XA_GRP (N_ROWS * E_DIM / 8)   // 1,048,576
#define WB_GRP (Q_ROWS * E_DIM / 8)   //   524,288
__global__ void convert_bf16_kernel(const float* __restrict__ X,
                                    const float* __restrict__ W) {
    int t = blockIdx.x * blockDim.x + threadIdx.x;
    if (t >= XA_GRP + WB_GRP) return;
    const float4* src;
    __nv_bfloat162* dst;
    int g;
    if (t < XA_GRP) {
        g = t; src = reinterpret_cast<const float4*>(X);
        dst = reinterpret_cast<__nv_bfloat162*>(g_xb);
    } else {
        g = t - XA_GRP; src = reinterpret_cast<const float4*>(W);
        dst = reinterpret_cast<__nv_bfloat162*>(g_wb);
    }
    float4 v0 = src[2 * g], v1 = src[2 * g + 1];
    __nv_bfloat162 o[4];
    o[0] = __floats2bfloat162_rn(v0.x, v0.y);
    o[1] = __floats2bfloat162_rn(v0.z, v0.w);
    o[2] = __floats2bfloat162_rn(v1.x, v1.y);
    o[3] = __floats2bfloat162_rn(v1.z, v1.w);
    reinterpret_cast<uint4*>(dst)[g] =
        make_uint4(*(uint32_t*)&o[0], *(uint32_t*)&o[1],
                   *(uint32_t*)&o[2], *(uint32_t*)&o[3]);
}

// ---------------------------------------------------------------------------
// Kernel 3: bf16 screening GEMM via mma.sync (HMMA pipe).
// s[n,q] = w_sq[q] - 2 * dot_bf16(x[n], w[q]), stored fp16.
// Grid: (Q/128, N/128). 256 thr, 8 warps (2 m x 4 n), warp tile 64x32.
// cp.async double-buffered smem, padded stride 80B (16B-aligned rows).
// ---------------------------------------------------------------------------
__global__ void __launch_bounds__(GEMM_THREADS, 1)
screen_gemm_kernel() {
    __shared__ __align__(16) char smA[2][BM * ROWB];
    __shared__ __align__(16) char smB[2][BN * ROWB];

    const int tid = threadIdx.x;
    const int lane = tid & 31;
    const int wid = tid >> 5;
    const int warpM = wid >> 2;          // 0..1
    const int warpN = wid & 3;           // 0..3
    const int mBase = blockIdx.y * BM;
    const int nBase = blockIdx.x * BN;

    const uint32_t sA[2] = { smem_u32(smA[0]), smem_u32(smA[1]) };
    const uint32_t sB[2] = { smem_u32(smB[0]), smem_u32(smB[1]) };

    // loader: 512 16B chunks each for A and B; 2+2 per thread.
    // chunk c -> row = c>>2, kc = c&3 (16B within the 64B k-slab)
    auto load_stage = [&](int kt, int buf) {
        const int koff = kt * BK;           // element offset
        #pragma unroll
        for (int h = 0; h < 2; ++h) {
            int c = 2 * tid + h;
            int row = c >> 2, kc = c & 3;
            cp_async16(sA[buf] + row * ROWB + kc * 16,
                       (const char*)g_xb +
                       ((size_t)(mBase + row) * E_DIM + koff + kc * 8) * 2);
            cp_async16(sB[buf] + row * ROWB + kc * 16,
                       (const char*)g_wb +
                       ((size_t)(nBase + row) * E_DIM + koff + kc * 8) * 2);
        }
        cp_commit();
    };

    float acc[4][4][4];
    #pragma unroll
    for (int i = 0; i < 4; ++i)
        #pragma unroll
        for (int j = 0; j < 4; ++j)
            #pragma unroll
            for (int k = 0; k < 4; ++k) acc[i][j][k] = 0.f;

    load_stage(0, 0);

    const int NKT = E_DIM / BK;   // 16
    for (int kt = 0; kt < NKT; ++kt) {
        const int buf = kt & 1;
        if (kt + 1 < NKT) { load_stage(kt + 1, buf ^ 1); cp_wait<1>(); }
        else              { cp_wait<0>(); }
        __syncthreads();

        #pragma unroll
        for (int k16 = 0; k16 < 2; ++k16) {
            // A frags: 4 m16 tiles; group order lanes0-7/8-15/16-23/24-31
            // -> (r0-7,k0-7),(r8-15,k0-7),(r0-7,k8-15),(r8-15,k8-15) = a0..a3
            uint32_t af[4][4];
            #pragma unroll
            for (int i = 0; i < 4; ++i) {
                uint32_t addr = sA[buf] +
                    (warpM * 64 + i * 16 + (lane & 15)) * ROWB +
                    (k16 * 2 + (lane >> 4)) * 16;
                ldm_x4(af[i][0], af[i][1], af[i][2], af[i][3], addr);
            }
            // B frags: 2 ldmatrix.x4, each covers two n8 tiles:
            // r0=(n0-7,k0-7) r1=(n0-7,k8-15) r2=(n8-15,k0-7) r3=(n8-15,k8-15)
            uint32_t bf[2][4];
            #pragma unroll
            for (int j = 0; j < 2; ++j) {
                uint32_t addr = sB[buf] +
                    (warpN * 32 + j * 16 + (lane & 7) + ((lane >> 4) << 3)) * ROWB +
                    (k16 * 2 + ((lane >> 3) & 1)) * 16;
                ldm_x4(bf[j][0], bf[j][1], bf[j][2], bf[j][3], addr);
            }
            #pragma unroll
            for (int i = 0; i < 4; ++i)
                #pragma unroll
                for (int jj = 0; jj < 4; ++jj) {
                    uint32_t bb[2] = { bf[jj >> 1][(jj & 1) * 2 + 0],
                                       bf[jj >> 1][(jj & 1) * 2 + 1] };
                    mma_bf16(acc[i][jj], af[i], bb);
                }
        }
        __syncthreads();
    }

    // epilogue: s = wsq - 2*dot, fp16, row-major [n][8192]
    const int r = lane >> 2, cp = lane & 3;
    float wsq0[4], wsq1[4];
    #pragma unroll
    for (int jj = 0; jj < 4; ++jj) {
        int q = nBase + warpN * 32 + jj * 8 + cp * 2;
        wsq0[jj] = g_wsq[q];
        wsq1[jj] = g_wsq[q + 1];
    }
    #pragma unroll
    for (int i = 0; i < 4; ++i) {
        const int ra = mBase + warpM * 64 + i * 16 + r;
        const int rb = ra + 8;
        #pragma unroll
        for (int jj = 0; jj < 4; ++jj) {
            const int q = nBase + warpN * 32 + jj * 8 + cp * 2;
            __half2 h0 = __floats2half2_rn(
                fmaf(-2.0f, acc[i][jj][0], wsq0[jj]),
                fmaf(-2.0f, acc[i][jj][1], wsq1[jj]));
            __half2 h1 = __floats2half2_rn(
                fmaf(-2.0f, acc[i][jj][2], wsq0[jj]),
                fmaf(-2.0f, acc[i][jj][3], wsq1[jj]));
            g_s[(size_t)ra * (Q_ROWS / 2) + (q >> 1)] = h0;
            g_s[(size_t)rb * (Q_ROWS / 2) + (q >> 1)] = h1;
        }
    }
}

// ---------------------------------------------------------------------------
// Kernel 4: per-row candidate selection + exact fp32 verification.
// One warp per row. Pass 1: min of fp16 screen row. Pass 2: every q with
// s <= min+MARGIN gets an exact fp32 distance (same rounding as reference),
// argmin with lowest-index tie rule.
// ---------------------------------------------------------------------------
__global__ void __launch_bounds__(256)
select_kernel(const float* __restrict__ X, const float* __restrict__ W) {
    const int lane = threadIdx.x & 31;
    const int row = blockIdx.x * 8 + (threadIdx.x >> 5);
    const uint4* srow = reinterpret_cast<const uint4*>(
        g_s + (size_t)row * (Q_ROWS / 2));

    // pass 1: min
    float mn = __int_as_float(0x7f800000);
    #pragma unroll 4
    for (int i = 0; i < 32; ++i) {
        uint4 v = srow[lane + 32 * i];
        const uint32_t* p = &v.x;
        #pragma unroll
        for (int j = 0; j < 4; ++j) {
            __half2 h = *reinterpret_cast<const __half2*>(&p[j]);
            float a = __low2float(h), b = __high2float(h);
            mn = fminf(mn, fminf(a, b));
        }
    }
    #pragma unroll
    for (int o = 16; o > 0; o >>= 1)
        mn = fminf(mn, __shfl_xor_sync(0xffffffffu, mn, o));
    const float thr = mn + MARGIN;

    const float xs = g_xsq[row];
    const float4* xr = reinterpret_cast<const float4*>(X + (size_t)row * E_DIM);
    float bestv = __int_as_float(0x7f800000);
    int bestq = 0x7fffffff;

    // pass 2: candidates -> exact distance (warp-cooperative dot)
    for (int i = 0; i < 32; ++i) {
        uint4 v = srow[lane + 32 * i];
        const uint32_t* p = &v.x;
        #pragma unroll
        for (int j = 0; j < 8; ++j) {
            __half2 h = *reinterpret_cast<const __half2*>(&p[j >> 1]);
            float sv = (j & 1) ? __high2float(h) : __low2float(h);
            int myq = (lane + 32 * i) * 8 + j;
            unsigned m = __ballot_sync(0xffffffffu, sv <= thr);
            while (m) {
                int src = __ffs(m) - 1;
                m &= m - 1;
                int q = __shfl_sync(0xffffffffu, myq, src);
                const float4* wr =
                    reinterpret_cast<const float4*>(W + (size_t)q * E_DIM);
                float part = 0.f;
                #pragma unroll
                for (int c = 0; c < 4; ++c) {
                    float4 a = xr[lane + 32 * c];
                    float4 b = wr[lane + 32 * c];
                    part = fmaf(a.x, b.x, part);
                    part = fmaf(a.y, b.y, part);
                    part = fmaf(a.z, b.z, part);
                    part = fmaf(a.w, b.w, part);
                }
                #pragma unroll
                for (int o = 16; o > 0; o >>= 1)
                    part += __shfl_xor_sync(0xffffffffu, part, o);
                float vv = fmaf(-2.0f, part, xs);   // matches ref rounding
                vv = vv + g_wsq[q];
                if (vv < bestv || (vv == bestv && q < bestq)) {
                    bestv = vv; bestq = q;
                }
            }
        }
    }
    if (lane == 0) g_idx[row] = bestq;
}

// ---------------------------------------------------------------------------
// Kernel 5: gather codebook rows + emit idx (unchanged).
// ---------------------------------------------------------------------------
__global__ void gather_kernel(const float* __restrict__ W,
                              float* __restrict__ out,
                              int N, long long total) {
    long long p = (long long)blockIdx.x * blockDim.x + threadIdx.x;
    if (p >= total) return;
    const long long ne = (long long)N * E_DIM;
    if (p < ne) {
        int n = (int)(p >> 9);
        int e = (int)(p & 511);
        out[p] = W[(size_t)g_idx[n] * E_DIM + e];
    } else if (p < ne + N) {
        out[p] = (float)g_idx[p - ne];
    } else {
        out[p] = 0.f;
    }
}

// ---------------------------------------------------------------------------
extern "C" void kernel_launch(void* const* d_in, const int* in_sizes, int n_in,
                              void* d_out, int out_size) {
    const float* x = (const float*)d_in[0];   // (8,2048,512) fp32
    const float* w = (const float*)d_in[1];   // (8192,512)  fp32
    const int N = in_sizes[0] / E_DIM;        // 16384
    const int Q = in_sizes[1] / E_DIM;        // 8192

    sumsq_kernel<<<N + Q, 128>>>(x, w, N);

    {
        const int groups = XA_GRP + WB_GRP;
        convert_bf16_kernel<<<(groups + 255) / 256, 256>>>(x, w);
    }

    dim3 grid(Q / BN, N / BM);                // (64, 128)
    screen_gemm_kernel<<<grid, GEMM_THREADS>>>();

    select_kernel<<<N / 8, 256>>>(x, w);

    const long long total = (long long)out_size;
    const int thr = 256;
    const int blocks = (int)((total + thr - 1) / thr);
    gather_kernel<<<blocks, thr>>>(w, (float*)d_out, N, total);
}